// round 4
// baseline (speedup 1.0000x reference)
#include <cuda_runtime.h>

// ---------------------------------------------------------------------------
// VectorQuantizer: N=16384 queries (16x32x32), D=256, K=8192 codes.
// Outputs (fp32, concatenated in d_out):
//   [0, 4194304)             quantized (STE), NCHW [16,256,32,32]
//   [4194304, +16384)        indices (as float), [16,1024]
//   [4210688]                vq_loss scalar
//
// Strategy: fp32 FFMA2 GEMM -> full dist matrix; per-query candidate set
// within eps of min; exact fp64 rescore emulating the reference's fp32
// rounding (||f||^2 - 2 f.e + ||e||^2, left-to-right) incl. first-index ties.
// ---------------------------------------------------------------------------

#define NQ   16384
#define KC   8192
#define DIM  256
#define BQ   128
#define BK   128
#define DC   64

#define QUANT_ELEMS (NQ * DIM)
#define IDX_OFF     QUANT_ELEMS
#define LOSS_OFF    (QUANT_ELEMS + NQ)

#define EPS_SEL 6.5e-5f     // ~2 ulps of 256; covers ref quantization + gemm err
#define MAXCAND 128

__device__ float g_Bt[DIM * KC];              // transposed codebook [D][K]
__device__ float g_cnorm[KC];                 // ||e_k||^2 (fp32, selection only)
__device__ float g_dist[(size_t)NQ * KC];     // 512 MB scratch dist matrix
__device__ int   g_fin[NQ];                   // final indices
__device__ float g_loss;

// ---- packed f32x2 helpers (FFMA2, sm_100+) --------------------------------
#define PACK2(dst, lo, hi) \
    asm("mov.b64 %0, {%1, %2};" : "=l"(dst) : "f"(lo), "f"(hi))
#define UNPACK2(lo, hi, src) \
    asm("mov.b64 {%0, %1}, %2;" : "=f"(lo), "=f"(hi) : "l"(src))
#define FMA2(acc, a, b) \
    asm("fma.rn.f32x2 %0, %1, %2, %3;" : "=l"(acc) : "l"(a), "l"(b), "l"(acc))

// ---------------------------------------------------------------------------
__global__ void zero_loss_kernel() { g_loss = 0.0f; }

__global__ void transpose_codebook(const float* __restrict__ cb) {
    __shared__ float tile[32][33];
    int kbase = blockIdx.x * 32;
    int dbase = blockIdx.y * 32;
    int tx = threadIdx.x, ty = threadIdx.y;   // block (32, 8)
#pragma unroll
    for (int r = 0; r < 4; r++)
        tile[ty + 8 * r][tx] = cb[(size_t)(kbase + ty + 8 * r) * DIM + dbase + tx];
    __syncthreads();
#pragma unroll
    for (int r = 0; r < 4; r++)
        g_Bt[(size_t)(dbase + ty + 8 * r) * KC + kbase + tx] = tile[tx][ty + 8 * r];
}

__global__ void code_norms(const float* __restrict__ cb) {
    int warp = threadIdx.x >> 5, lane = threadIdx.x & 31;
    int k = blockIdx.x * 8 + warp;
    const float* row = cb + (size_t)k * DIM;
    float s = 0.0f;
#pragma unroll
    for (int i = 0; i < DIM / 32; i++) {
        float v = row[lane + 32 * i];
        s += v * v;
    }
#pragma unroll
    for (int o = 16; o > 0; o >>= 1) s += __shfl_xor_sync(0xFFFFFFFFu, s, o);
    if (lane == 0) g_cnorm[k] = s;
}

// ---------------------------------------------------------------------------
// Pass 1: distance GEMM. One CTA = 128 queries x all 8192 codes; writes
// d = ||e||^2 - 2 f.e (fp32) to g_dist. FFMA2 packed row-pair accumulators.
// ---------------------------------------------------------------------------
__global__ void __launch_bounds__(256, 1)
vq_gemm(const float* __restrict__ hidden, float* __restrict__ out) {
    extern __shared__ float sm[];
    float* As = sm;                 // [256 d][128 q]
    float* Bs = sm + DIM * BQ;      // [64 kk][128 c]

    const int tid = threadIdx.x;
    const int tx = tid & 15, ty = tid >> 4;
    const int qbase = blockIdx.x * BQ;
    const int b = qbase >> 10;
    const int hwbase = qbase & 1023;

    const float* hsrc = hidden + (size_t)b * (DIM * 1024) + hwbase;
    for (int i = tid; i < DIM * BQ; i += 256) {
        int d = i >> 7, q = i & 127;
        As[i] = hsrc[(d << 10) + q];
    }
    __syncthreads();

    for (int ct = 0; ct < KC / BK; ct++) {
        const int cbase = ct * BK;
        unsigned long long acc[4][8];
#pragma unroll
        for (int p = 0; p < 4; p++)
#pragma unroll
            for (int j = 0; j < 8; j++) acc[p][j] = 0ull;

#pragma unroll 1
        for (int dc = 0; dc < DIM / DC; dc++) {
            __syncthreads();
            const int dbase = dc * DC;
            for (int i = tid; i < DC * BK / 4; i += 256) {
                int kk = i >> 5, c4 = i & 31;
                ((float4*)Bs)[i] =
                    *(const float4*)&g_Bt[(size_t)(dbase + kk) * KC + cbase + (c4 << 2)];
            }
            __syncthreads();

#pragma unroll 8
            for (int kk = 0; kk < DC; kk++) {
                const float* arow = As + (dbase + kk) * BQ + ty * 8;
                longlong2 av0 = *(const longlong2*)(arow);
                longlong2 av1 = *(const longlong2*)(arow + 4);
                unsigned long long ap[4];
                ap[0] = (unsigned long long)av0.x;
                ap[1] = (unsigned long long)av0.y;
                ap[2] = (unsigned long long)av1.x;
                ap[3] = (unsigned long long)av1.y;

                const float* brow = Bs + kk * BK + tx * 8;
                float4 b0 = *(const float4*)(brow);
                float4 b1 = *(const float4*)(brow + 4);
                unsigned long long bd[8];
                PACK2(bd[0], b0.x, b0.x);
                PACK2(bd[1], b0.y, b0.y);
                PACK2(bd[2], b0.z, b0.z);
                PACK2(bd[3], b0.w, b0.w);
                PACK2(bd[4], b1.x, b1.x);
                PACK2(bd[5], b1.y, b1.y);
                PACK2(bd[6], b1.z, b1.z);
                PACK2(bd[7], b1.w, b1.w);

#pragma unroll
                for (int j = 0; j < 8; j++)
#pragma unroll
                    for (int p = 0; p < 4; p++)
                        FMA2(acc[p][j], ap[p], bd[j]);
            }
        }

        // d = ||e||^2 - 2<f,e>; store tile to g_dist
#pragma unroll
        for (int p = 0; p < 4; p++) {
            float d0[8], d1[8];
#pragma unroll
            for (int j = 0; j < 8; j++) {
                const int idx = cbase + tx * 8 + j;
                const float cn = g_cnorm[idx];
                float s0, s1;
                UNPACK2(s0, s1, acc[p][j]);
                d0[j] = cn - 2.0f * s0;
                d1[j] = cn - 2.0f * s1;
            }
            size_t r0 = (size_t)(qbase + ty * 8 + 2 * p) * KC + cbase + tx * 8;
            size_t r1 = r0 + KC;
            *(float4*)&g_dist[r0]     = make_float4(d0[0], d0[1], d0[2], d0[3]);
            *(float4*)&g_dist[r0 + 4] = make_float4(d0[4], d0[5], d0[6], d0[7]);
            *(float4*)&g_dist[r1]     = make_float4(d1[0], d1[1], d1[2], d1[3]);
            *(float4*)&g_dist[r1 + 4] = make_float4(d1[4], d1[5], d1[6], d1[7]);
        }
    }
}

// ---------------------------------------------------------------------------
// Pass 2: per-query candidate selection + exact fp64 rescore with faithful
// fp32 rounding emulation of the reference:
//   R = fp32( fp32(fnorm - 2*dot) + cnorm ), argmin, first-index ties.
// One warp per query.
// ---------------------------------------------------------------------------
__global__ void __launch_bounds__(256)
vq_select(const float* __restrict__ hidden, const float* __restrict__ cb,
          float* __restrict__ out) {
    __shared__ int s_cand[8][MAXCAND];
    __shared__ int s_cnt[8];

    const int w = threadIdx.x >> 5;
    const int lane = threadIdx.x & 31;
    const int q = blockIdx.x * 8 + w;

    const float* drow = g_dist + (size_t)q * KC;

    // sweep 1: fp32 min
    float mn = 3.4e38f;
    for (int i = 0; i < KC / 32; i++)
        mn = fminf(mn, drow[i * 32 + lane]);
#pragma unroll
    for (int o = 16; o > 0; o >>= 1)
        mn = fminf(mn, __shfl_xor_sync(0xFFFFFFFFu, mn, o));
    const float thresh = mn + EPS_SEL;

    // sweep 2: collect candidates (ascending k)
    if (lane == 0) s_cnt[w] = 0;
    __syncwarp();
    for (int i = 0; i < KC / 32; i++) {
        int k = i * 32 + lane;
        bool c = (drow[k] <= thresh);
        unsigned m = __ballot_sync(0xFFFFFFFFu, c);
        if (m) {
            int base = s_cnt[w];
            __syncwarp();
            if (c) {
                int pos = base + __popc(m & ((1u << lane) - 1u));
                if (pos < MAXCAND) s_cand[w][pos] = k;
            }
            if (lane == 0) s_cnt[w] = min(MAXCAND, base + __popc(m));
        }
        __syncwarp();
    }

    // preload query column + fp64 fnorm
    const int b = q >> 10, hw = q & 1023;
    const float* xcol = hidden + (size_t)b * (DIM * 1024) + hw;
    float xr[8];
    double fn = 0.0;
#pragma unroll
    for (int t = 0; t < 8; t++) {
        float v = xcol[(size_t)(lane * 8 + t) * 1024];
        xr[t] = v;
        fn += (double)v * (double)v;
    }
#pragma unroll
    for (int o = 16; o > 0; o >>= 1)
        fn += __shfl_xor_sync(0xFFFFFFFFu, fn, o);
    const float fn32 = (float)fn;

    // rescore candidates exactly
    float bestR = 3.4e38f;
    int bestK = 0;
    const int cnt = s_cnt[w];
    for (int c = 0; c < cnt; c++) {
        int k = s_cand[w][c];
        const float4* er = (const float4*)(cb + (size_t)k * DIM + lane * 8);
        float4 e0 = er[0], e1 = er[1];
        float ev[8] = {e0.x, e0.y, e0.z, e0.w, e1.x, e1.y, e1.z, e1.w};
        double dot = 0.0, cn = 0.0;
#pragma unroll
        for (int t = 0; t < 8; t++) {
            double ed = (double)ev[t];
            dot += (double)xr[t] * ed;
            cn += ed * ed;
        }
#pragma unroll
        for (int o = 16; o > 0; o >>= 1) {
            dot += __shfl_xor_sync(0xFFFFFFFFu, dot, o);
            cn  += __shfl_xor_sync(0xFFFFFFFFu, cn, o);
        }
        // reference rounding: (fnorm - 2*dot) + cnorm, left-to-right fp32
        float t1 = __fsub_rn(fn32, __fmul_rn(2.0f, (float)dot));
        float R  = __fadd_rn(t1, (float)cn);
        if (R < bestR) { bestR = R; bestK = k; }   // ascending k => first-min ties
    }

    if (lane == 0) {
        g_fin[q] = bestK;
        out[IDX_OFF + q] = (float)bestK;
    }
}

// ---------------------------------------------------------------------------
// Pass 3: gather + straight-through estimator (faithful fp32 rounding:
// out = x + (q - x)) + vq loss accumulation. One CTA = 128 queries.
// ---------------------------------------------------------------------------
__global__ void __launch_bounds__(256)
vq_output(const float* __restrict__ hidden, const float* __restrict__ cb,
          float* __restrict__ out) {
    __shared__ float Es[64 * 129];
    __shared__ int s_fin[128];
    __shared__ float lred[256];

    const int tid = threadIdx.x;
    const int qbase = blockIdx.x * BQ;
    const int b = qbase >> 10, hwbase = qbase & 1023;

    if (tid < 128) s_fin[tid] = g_fin[qbase + tid];
    __syncthreads();

    const float* hsrc = hidden + (size_t)b * (DIM * 1024) + hwbase;
    float* obase = out + (size_t)b * (DIM * 1024) + hwbase;

    float lsum = 0.0f;
    for (int dchunk = 0; dchunk < 4; dchunk++) {
        const int dbase = dchunk * 64;
        for (int i = tid; i < 128 * 64; i += 256) {
            int qq = i >> 6, dd = i & 63;
            Es[dd * 129 + qq] = cb[(size_t)s_fin[qq] * DIM + dbase + dd];
        }
        __syncthreads();
        for (int i = tid; i < 64 * 128; i += 256) {
            int dd = i >> 7, qq = i & 127;
            int d = dbase + dd;
            float x = hsrc[(d << 10) + qq];
            float e = Es[dd * 129 + qq];
            float df = __fsub_rn(e, x);       // (q - x), same rounding as ref
            lsum += df * df;
            obase[(d << 10) + qq] = __fadd_rn(x, df);   // STE: x + (q - x)
        }
        __syncthreads();
    }

    lred[tid] = lsum;
    __syncthreads();
    for (int s = 128; s > 0; s >>= 1) {
        if (tid < s) lred[tid] += lred[tid + s];
        __syncthreads();
    }
    if (tid == 0) atomicAdd(&g_loss, lred[0]);
}

__global__ void finalize_loss(float* __restrict__ out) {
    out[LOSS_OFF] = 1.25f * g_loss / (float)(NQ * DIM);
}

// ---------------------------------------------------------------------------
extern "C" void kernel_launch(void* const* d_in, const int* in_sizes, int n_in,
                              void* d_out, int out_size) {
    const float* hidden = (const float*)d_in[0];
    const float* cb     = (const float*)d_in[1];
    if (n_in >= 2 && in_sizes[0] == KC * DIM) {   // inputs swapped?
        const float* t = hidden; hidden = cb; cb = t;
    }
    float* out = (float*)d_out;

    const int smem_bytes = (DIM * BQ + DC * BK) * (int)sizeof(float);  // 160 KB
    cudaFuncSetAttribute(vq_gemm, cudaFuncAttributeMaxDynamicSharedMemorySize,
                         smem_bytes);

    zero_loss_kernel<<<1, 1>>>();
    transpose_codebook<<<dim3(KC / 32, DIM / 32), dim3(32, 8)>>>(cb);
    code_norms<<<KC / 8, 256>>>(cb);
    vq_gemm<<<NQ / BQ, 256, smem_bytes>>>(hidden, out);
    vq_select<<<NQ / 8, 256>>>(hidden, cb, out);
    vq_output<<<NQ / BQ, 256>>>(hidden, cb, out);
    finalize_loss<<<1, 1>>>(out);
}